// round 7
// baseline (speedup 1.0000x reference)
#include <cuda_runtime.h>
#include <cuda_bf16.h>
#include <cuda_fp16.h>
#include <cstdint>

#define BATCH 4
#define NPIX  4096
#define CATT  128
#define EPS   1e-5f

// ---------------- device scratch ------------------------------------------
__device__ float g_tmp[BATCH * 16 * 128 * 128];
__device__ float g_f  [BATCH * 48 * NPIX];
__device__ __half g_q [(size_t)BATCH * NPIX * CATT];    // [b][i][c]
__device__ __half g_k [(size_t)BATCH * NPIX * CATT];    // [b][j][c]
__device__ __half g_v [(size_t)BATCH * CATT * NPIX];    // [b][c][j]
__device__ __half g_att[(size_t)BATCH * NPIX * NPIX];   // fp16 att (134 MB)
__device__ float g_ov [BATCH * CATT * NPIX];            // V*p
__device__ float g_sv [2][BATCH * CATT * NPIX];         // split-K partials

// ---------------- helpers --------------------------------------------------
__device__ __forceinline__ uint32_t smem_u32(const void* smem_ptr) {
    uint32_t addr;
    asm("{ .reg .u64 tmp; cvta.to.shared.u64 tmp, %1; cvt.u32.u64 %0, tmp; }"
        : "=r"(addr) : "l"(smem_ptr));
    return addr;
}
__device__ __forceinline__ void ldmx4(uint32_t* r, uint32_t addr) {
    asm volatile("ldmatrix.sync.aligned.m8n8.x4.shared.b16 {%0,%1,%2,%3}, [%4];"
        : "=r"(r[0]), "=r"(r[1]), "=r"(r[2]), "=r"(r[3]) : "r"(addr));
}
__device__ __forceinline__ void mma16816(float* c, const uint32_t* a,
                                         const uint32_t* b) {
    asm volatile(
        "mma.sync.aligned.m16n8k16.row.col.f32.f16.f16.f32 "
        "{%0,%1,%2,%3}, {%4,%5,%6,%7}, {%8,%9}, {%0,%1,%2,%3};"
        : "+f"(c[0]), "+f"(c[1]), "+f"(c[2]), "+f"(c[3])
        : "r"(a[0]), "r"(a[1]), "r"(a[2]), "r"(a[3]), "r"(b[0]), "r"(b[1]));
}
__device__ __forceinline__ void cp16(uint32_t dst, const void* src) {
    asm volatile("cp.async.ca.shared.global [%0], [%1], 16;"
                 :: "r"(dst), "l"(src) : "memory");
}
#define CP_COMMIT() asm volatile("cp.async.commit_group;" ::: "memory")
#define CP_WAIT1()  asm volatile("cp.async.wait_group 1;" ::: "memory")
#define CP_WAIT0()  asm volatile("cp.async.wait_group 0;" ::: "memory")

// packed fp32x2 (sm_100 baseline)
typedef unsigned long long ull;
__device__ __forceinline__ ull pack2(float x, float y) {
    ull r; asm("mov.b64 %0, {%1, %2};" : "=l"(r) : "f"(x), "f"(y)); return r;
}
__device__ __forceinline__ void unpack2(ull v, float& x, float& y) {
    asm("mov.b64 {%0, %1}, %2;" : "=f"(x), "=f"(y) : "l"(v));
}
__device__ __forceinline__ ull fma2(ull a, ull b, ull c) {
    ull d; asm("fma.rn.f32x2 %0, %1, %2, %3;" : "=l"(d) : "l"(a), "l"(b), "l"(c));
    return d;
}

#define ST128 136
#define ST64  72
#define G1_PLANE (128 * ST128 * 2)
#define G1_SMEM  (2 * G1_PLANE)
#define G2_PLANE (128 * ST64 * 2)
#define G2_BUF   (2 * G2_PLANE)
#define G2_SMEM  (2 * G2_BUF)

__device__ __forceinline__ uint32_t pk2h(float a, float b) {
    __half2 h = __floats2half2_rn(a, b);
    return *(uint32_t*)&h;
}

// ---------------------------------------------------------------------------
// Kernel 1: conv3x3 + BN + PReLU  (f32x2 packed: weight pairs pre-packed)
// ---------------------------------------------------------------------------
__global__ __launch_bounds__(256) void k_conv3(
    const float* __restrict__ em, const float* __restrict__ en_w,
    const float* __restrict__ en_b, const float* __restrict__ bn1_g,
    const float* __restrict__ bn1_b, const float* __restrict__ bn1_m,
    const float* __restrict__ bn1_v, const float* __restrict__ prelu1)
{
    __shared__ __align__(8) float2 ws2[8 * 64 * 9];   // [o2][ci][k]
    __shared__ float tile[4][18 * 18];
    const int tid = threadIdx.y * 16 + threadIdx.x;
    for (int idx = tid; idx < 8 * 64 * 9; idx += 256) {
        int o2 = idx / 576, rem = idx % 576;
        int ci = rem / 9, k = rem % 9;
        ws2[idx] = make_float2(en_w[(2 * o2) * 576 + ci * 9 + k],
                               en_w[(2 * o2 + 1) * 576 + ci * 9 + k]);
    }

    const int b  = blockIdx.z;
    const int gx = blockIdx.x * 16 + threadIdx.x;
    const int gy = blockIdx.y * 16 + threadIdx.y;

    ull acc2[8];
#pragma unroll
    for (int o = 0; o < 8; o++) acc2[o] = 0ull;
    const float* emb = em + (size_t)b * 64 * 128 * 128;

    for (int ci0 = 0; ci0 < 64; ci0 += 4) {
        __syncthreads();
        for (int idx = tid; idx < 4 * 324; idx += 256) {
            int c = idx / 324, rem = idx - c * 324;
            int r = rem / 18, cc = rem - r * 18;
            int yy = (int)blockIdx.y * 16 + r - 1;
            int xx = (int)blockIdx.x * 16 + cc - 1;
            float v = 0.f;
            if (yy >= 0 && yy < 128 && xx >= 0 && xx < 128)
                v = emb[(size_t)(ci0 + c) * 16384 + yy * 128 + xx];
            tile[c][rem] = v;
        }
        __syncthreads();
#pragma unroll
        for (int c = 0; c < 4; c++) {
            ull t2[9];
#pragma unroll
            for (int kh = 0; kh < 3; kh++)
#pragma unroll
                for (int kw = 0; kw < 3; kw++) {
                    float tv = tile[c][(threadIdx.y + kh) * 18 + threadIdx.x + kw];
                    t2[kh * 3 + kw] = pack2(tv, tv);
                }
#pragma unroll
            for (int o2 = 0; o2 < 8; o2++) {
                const ull* wp = (const ull*)&ws2[(o2 * 64 + ci0 + c) * 9];
#pragma unroll
                for (int k = 0; k < 9; k++)
                    acc2[o2] = fma2(wp[k], t2[k], acc2[o2]);
            }
        }
    }

    const float a = prelu1[0];
#pragma unroll
    for (int o2 = 0; o2 < 8; o2++) {
        float v0, v1;
        unpack2(acc2[o2], v0, v1);
#pragma unroll
        for (int h = 0; h < 2; h++) {
            int o = 2 * o2 + h;
            float y  = (h ? v1 : v0) + en_b[o];
            float sc = bn1_g[o] * rsqrtf(bn1_v[o] + EPS);
            y = (y - bn1_m[o]) * sc + bn1_b[o];
            y = (y >= 0.f) ? y : a * y;
            g_tmp[(((size_t)b * 16 + o) * 128 + gy) * 128 + gx] = y;
        }
    }
}

// ---------------------------------------------------------------------------
// Kernel 2: build f
// ---------------------------------------------------------------------------
__global__ __launch_bounds__(256) void k_build_f(
    const float* __restrict__ dm, const float* __restrict__ de_w,
    const float* __restrict__ de_b, const float* __restrict__ dw_w,
    const float* __restrict__ dw_b)
{
    const int b  = blockIdx.z;
    const int ch = blockIdx.y;
    const int i  = blockIdx.x * 256 + threadIdx.x;
    float out;
    if (ch < 16) {
        const int ph = i >> 6, pw = i & 63;
        float m = -1e30f;
        const float* tb = g_tmp + ((size_t)b * 16 + ch) * 16384;
#pragma unroll
        for (int dy = 0; dy < 3; dy++) {
            int y = 2 * ph - 1 + dy;
            if (y < 0 || y > 127) continue;
#pragma unroll
            for (int dx = 0; dx < 3; dx++) {
                int x = 2 * pw - 1 + dx;
                if (x < 0 || x > 127) continue;
                m = fmaxf(m, tb[y * 128 + x]);
            }
        }
        out = m * dw_w[ch] + dw_b[ch];
    } else {
        const int co = ch - 16;
        float accv = de_b[co];
        const float* dmb = dm + (size_t)b * 128 * NPIX + i;
        const float* w   = de_w + co * 128;
#pragma unroll 8
        for (int c = 0; c < 128; c++)
            accv = fmaf(__ldg(w + c), __ldg(dmb + (size_t)c * NPIX), accv);
        out = accv;
    }
    g_f[((size_t)b * 48 + ch) * NPIX + i] = out;
}

// ---------------------------------------------------------------------------
// Kernel 3: QKV -> fp16 planes (+ g_ov = V*p); f32x2 packed weights
// grid (16, 3, 4), 256 thr
// ---------------------------------------------------------------------------
__global__ __launch_bounds__(256) void k_qkv_t(
    const float* __restrict__ q_w, const float* __restrict__ q_b,
    const float* __restrict__ k_w, const float* __restrict__ k_b,
    const float* __restrict__ v_w, const float* __restrict__ v_b,
    const float* __restrict__ p)
{
    __shared__ __align__(8) float2 ws2[64 * 48];   // [c2][k] channel pairs
    __shared__ float bsm[128];
    const int b    = blockIdx.z;
    const int proj = blockIdx.y;
    const int tid  = threadIdx.x;
    const int i    = blockIdx.x * 256 + tid;

    const float* w  = (proj == 0) ? q_w : (proj == 1) ? k_w : v_w;
    const float* bb = (proj == 0) ? q_b : (proj == 1) ? k_b : v_b;
    for (int idx = tid; idx < 64 * 48; idx += 256) {
        int c2 = idx / 48, k = idx % 48;
        ws2[idx] = make_float2(w[(2 * c2) * 48 + k], w[(2 * c2 + 1) * 48 + k]);
    }
    if (tid < 128) bsm[tid] = bb[tid];
    __syncthreads();

    float fv[48];
#pragma unroll
    for (int k = 0; k < 48; k++)
        fv[k] = g_f[((size_t)b * 48 + k) * NPIX + i];

    float res[128];
#pragma unroll
    for (int g = 0; g < 4; g++) {
        ull acc2[16];
#pragma unroll
        for (int c2 = 0; c2 < 16; c2++)
            acc2[c2] = pack2(bsm[(g * 16 + c2) * 2], bsm[(g * 16 + c2) * 2 + 1]);
        for (int k = 0; k < 48; k++) {
            ull t2 = pack2(fv[k], fv[k]);
            const ull* wp = (const ull*)&ws2[g * 16 * 48 + k];
#pragma unroll
            for (int c2 = 0; c2 < 16; c2++)
                acc2[c2] = fma2(wp[c2 * 48], t2, acc2[c2]);
        }
#pragma unroll
        for (int c2 = 0; c2 < 16; c2++)
            unpack2(acc2[c2], res[(g * 16 + c2) * 2], res[(g * 16 + c2) * 2 + 1]);
    }

    if (proj < 2) {
        __half* dst = ((proj == 0) ? g_q : g_k) + ((size_t)b * NPIX + i) * CATT;
#pragma unroll
        for (int c8 = 0; c8 < 16; c8++) {
            uint4 pkt;
            __half* hb = (__half*)&pkt;
#pragma unroll
            for (int cc = 0; cc < 8; cc++)
                hb[cc] = __float2half_rn(res[c8 * 8 + cc]);
            *(uint4*)(dst + c8 * 8) = pkt;
        }
    } else {
        const float pv = p[(size_t)b * NPIX + i];
        for (int c = 0; c < 128; c++) {
            size_t off = ((size_t)b * CATT + c) * NPIX + i;
            g_v[off]  = __float2half_rn(res[c]);
            g_ov[off] = res[c] * pv;
        }
    }
}

// ---------------------------------------------------------------------------
// Kernel 4: GEMM1 (fp16 HMMA): att = sigmoid(Q·K^T). grid (32,32,4), 256 thr.
// ---------------------------------------------------------------------------
__global__ __launch_bounds__(256, 2) void k_gemm1()
{
    extern __shared__ char smem[];
    const uint32_t su = smem_u32(smem);
    const uint32_t uA = su, uB = su + G1_PLANE;

    const int tid  = threadIdx.x;
    const int lane = tid & 31;
    const int warp = tid >> 5;
    const int wm = (warp & 1) * 64;
    const int wn = (warp >> 1) * 32;
    const int b  = blockIdx.z;
    const int i0 = blockIdx.y * 128;
    const int j0 = blockIdx.x * 128;

    const __half* A = g_q + ((size_t)b * NPIX + i0) * CATT;
    const __half* B = g_k + ((size_t)b * NPIX + j0) * CATT;

#pragma unroll
    for (int t = 0; t < 8; t++) {
        int idx = tid + t * 256;
        int r = idx >> 4, s = (idx & 15) * 8;
        uint32_t so = (uint32_t)(r * ST128 + s) * 2;
        cp16(uA + so, A + (size_t)r * CATT + s);
        cp16(uB + so, B + (size_t)r * CATT + s);
    }
    CP_COMMIT();
    CP_WAIT0();
    __syncthreads();

    float acc[4][4][4];
#pragma unroll
    for (int mi = 0; mi < 4; mi++)
#pragma unroll
        for (int ni = 0; ni < 4; ni++)
#pragma unroll
            for (int q = 0; q < 4; q++) acc[mi][ni][q] = 0.f;

#pragma unroll
    for (int kt = 0; kt < 8; kt++) {
        const int k0 = kt * 16;
        const uint32_t aoff =
            (uint32_t)(((wm + (lane & 15)) * ST128 + k0 + ((lane >> 4) << 3)) * 2);
        const uint32_t boff =
            (uint32_t)(((wn + (lane & 7) + ((lane >> 4) << 3)) * ST128 +
                        k0 + (((lane >> 3) & 1) << 3)) * 2);
        uint32_t a[4][4];
#pragma unroll
        for (int mi = 0; mi < 4; mi++)
            ldmx4(a[mi], uA + aoff + mi * 16 * ST128 * 2);
#pragma unroll
        for (int nj = 0; nj < 2; nj++) {
            uint32_t bfr[4];
            ldmx4(bfr, uB + boff + nj * 16 * ST128 * 2);
#pragma unroll
            for (int mi = 0; mi < 4; mi++) {
                mma16816(acc[mi][2 * nj],     a[mi], bfr);
                mma16816(acc[mi][2 * nj + 1], a[mi], bfr + 2);
            }
        }
    }

    __half* oh = g_att + ((size_t)b * NPIX + i0) * NPIX + j0;
#pragma unroll
    for (int mi = 0; mi < 4; mi++) {
        int r0 = wm + mi * 16 + (lane >> 2);
#pragma unroll
        for (int ni = 0; ni < 4; ni++) {
            int cc = wn + ni * 8 + 2 * (lane & 3);
            float s[4];
#pragma unroll
            for (int q = 0; q < 4; q++)
                s[q] = __fdividef(1.f, 1.f + __expf(-acc[mi][ni][q]));
            *(uint32_t*)(oh + (size_t)r0 * NPIX + cc)       = pk2h(s[0], s[1]);
            *(uint32_t*)(oh + (size_t)(r0 + 8) * NPIX + cc) = pk2h(s[2], s[3]);
        }
    }
}

// ---------------------------------------------------------------------------
// Kernel 5: GEMM2 (fp16 HMMA, split-K=2, no atomics -> g_sv[split])
// grid (2 jc, 32 it, 4), 256 thr
// ---------------------------------------------------------------------------
__global__ __launch_bounds__(256, 2) void k_gemm2()
{
    extern __shared__ char smem[];
    const uint32_t su = smem_u32(smem);

    const int tid  = threadIdx.x;
    const int lane = tid & 31;
    const int warp = tid >> 5;
    const int wm = (warp & 1) * 64;     // m = c
    const int wn = (warp >> 1) * 32;    // n = i
    const int b   = blockIdx.z;
    const int i0  = blockIdx.y * 128;
    const int spl = blockIdx.x;
    const int jc0 = spl * 2048;

    const __half* V = g_v + (size_t)b * CATT * NPIX;
    const __half* T = g_att + ((size_t)b * NPIX + i0) * NPIX;

    float acc[4][4][4];
#pragma unroll
    for (int mi = 0; mi < 4; mi++)
#pragma unroll
        for (int ni = 0; ni < 4; ni++)
#pragma unroll
            for (int q = 0; q < 4; q++) acc[mi][ni][q] = 0.f;

    auto stage = [&](int buf, int j0) {
        uint32_t base = su + buf * G2_BUF;
#pragma unroll
        for (int t = 0; t < 4; t++) {
            int idx = tid + t * 256;
            int r = idx >> 3, s = (idx & 7) * 8;
            uint32_t so = base + (uint32_t)(r * ST64 + s) * 2;
            cp16(so,            V + (size_t)r * NPIX + j0 + s);
            cp16(so + G2_PLANE, T + (size_t)r * NPIX + j0 + s);
        }
        CP_COMMIT();
    };

    stage(0, jc0);
    for (int st = 0; st < 32; st++) {
        if (st < 31) { stage((st + 1) & 1, jc0 + (st + 1) * 64); CP_WAIT1(); }
        else         { CP_WAIT0(); }
        __syncthreads();
        const uint32_t ub = su + (st & 1) * G2_BUF;
        const uint32_t uA = ub, uB = ub + G2_PLANE;
#pragma unroll
        for (int kt = 0; kt < 4; kt++) {
            const int k0 = kt * 16;
            const uint32_t aoff =
                (uint32_t)(((wm + (lane & 15)) * ST64 + k0 + ((lane >> 4) << 3)) * 2);
            const uint32_t boff =
                (uint32_t)(((wn + (lane & 7) + ((lane >> 4) << 3)) * ST64 +
                            k0 + (((lane >> 3) & 1) << 3)) * 2);
            uint32_t a[4][4];
#pragma unroll
            for (int mi = 0; mi < 4; mi++)
                ldmx4(a[mi], uA + aoff + mi * 16 * ST64 * 2);
#pragma unroll
            for (int nj = 0; nj < 2; nj++) {
                uint32_t bfr[4];
                ldmx4(bfr, uB + boff + nj * 16 * ST64 * 2);
#pragma unroll
                for (int mi = 0; mi < 4; mi++) {
                    mma16816(acc[mi][2 * nj],     a[mi], bfr);
                    mma16816(acc[mi][2 * nj + 1], a[mi], bfr + 2);
                }
            }
        }
        __syncthreads();
    }

    // epilogue: direct vectorized stores to split partial buffer
    float* ob = g_sv[spl] + ((size_t)b * CATT) * NPIX + i0;
#pragma unroll
    for (int mi = 0; mi < 4; mi++) {
        int c0 = wm + mi * 16 + (lane >> 2);
#pragma unroll
        for (int ni = 0; ni < 4; ni++) {
            int ii = wn + ni * 8 + 2 * (lane & 3);
            *(float2*)(ob + (size_t)c0 * NPIX + ii) =
                make_float2(acc[mi][ni][0], acc[mi][ni][1]);
            *(float2*)(ob + (size_t)(c0 + 8) * NPIX + ii) =
                make_float2(acc[mi][ni][2], acc[mi][ni][3]);
        }
    }
}

// ---------------------------------------------------------------------------
// Kernel 6: bottleneck 1x1 + BN + PReLU -> out (sums V*p + sv0 + sv1)
// ---------------------------------------------------------------------------
__global__ __launch_bounds__(256) void k_bt(
    const float* __restrict__ bt_w, const float* __restrict__ bt_b,
    const float* __restrict__ bn2_g, const float* __restrict__ bn2_b,
    const float* __restrict__ bn2_m, const float* __restrict__ bn2_v,
    const float* __restrict__ prelu2, float* __restrict__ out)
{
    __shared__ float ovs[128][64];
    const int b  = blockIdx.y;
    const int i0 = blockIdx.x * 64;
    const int tid = threadIdx.x;

    for (int idx = tid; idx < 128 * 64; idx += 256) {
        int c = idx >> 6, ii = idx & 63;
        size_t off = ((size_t)b * CATT + c) * NPIX + i0 + ii;
        ovs[c][ii] = g_ov[off] + g_sv[0][off] + g_sv[1][off];
    }
    __syncthreads();

    const int il = tid & 63, og = tid >> 6;
    float accs[16];
#pragma unroll
    for (int n = 0; n < 16; n++) accs[n] = 0.f;

    for (int c = 0; c < 128; c++) {
        float v = ovs[c][il];
#pragma unroll
        for (int n = 0; n < 16; n++)
            accs[n] = fmaf(__ldg(bt_w + (og * 16 + n) * 128 + c), v, accs[n]);
    }

    const float a = prelu2[0];
#pragma unroll
    for (int n = 0; n < 16; n++) {
        int o = og * 16 + n;
        float y  = accs[n] + bt_b[o];
        float sc = bn2_g[o] * rsqrtf(bn2_v[o] + EPS);
        y = (y - bn2_m[o]) * sc + bn2_b[o];
        y = (y >= 0.f) ? y : a * y;
        out[((size_t)b * 64 + o) * NPIX + i0 + il] = y;
    }
}

// ---------------------------------------------------------------------------
extern "C" void kernel_launch(void* const* d_in, const int* in_sizes, int n_in,
                              void* d_out, int out_size)
{
    const float* em     = (const float*)d_in[0];
    const float* dm     = (const float*)d_in[1];
    const float* p      = (const float*)d_in[2];
    const float* en_w   = (const float*)d_in[3];
    const float* en_b   = (const float*)d_in[4];
    const float* bn1_g  = (const float*)d_in[5];
    const float* bn1_b  = (const float*)d_in[6];
    const float* bn1_m  = (const float*)d_in[7];
    const float* bn1_v  = (const float*)d_in[8];
    const float* prelu1 = (const float*)d_in[9];
    const float* dw_w   = (const float*)d_in[10];
    const float* dw_b   = (const float*)d_in[11];
    const float* de_w   = (const float*)d_in[12];
    const float* de_b   = (const float*)d_in[13];
    const float* q_w    = (const float*)d_in[14];
    const float* q_b    = (const float*)d_in[15];
    const float* k_w    = (const float*)d_in[16];
    const float* k_b    = (const float*)d_in[17];
    const float* v_w    = (const float*)d_in[18];
    const float* v_b    = (const float*)d_in[19];
    const float* bt_w   = (const float*)d_in[20];
    const float* bt_b   = (const float*)d_in[21];
    const float* bn2_g  = (const float*)d_in[22];
    const float* bn2_b  = (const float*)d_in[23];
    const float* bn2_m  = (const float*)d_in[24];
    const float* bn2_v  = (const float*)d_in[25];
    const float* prelu2 = (const float*)d_in[26];

    cudaFuncSetAttribute(k_gemm1, cudaFuncAttributeMaxDynamicSharedMemorySize, G1_SMEM);
    cudaFuncSetAttribute(k_gemm2, cudaFuncAttributeMaxDynamicSharedMemorySize, G2_SMEM);

    k_conv3  <<<dim3(8, 8, 4),   dim3(16, 16)>>>(em, en_w, en_b, bn1_g, bn1_b,
                                                 bn1_m, bn1_v, prelu1);
    k_build_f<<<dim3(16, 48, 4), 256>>>(dm, de_w, de_b, dw_w, dw_b);
    k_qkv_t  <<<dim3(16, 3, 4),  256>>>(q_w, q_b, k_w, k_b, v_w, v_b, p);
    k_gemm1  <<<dim3(32, 32, 4), 256, G1_SMEM>>>();
    k_gemm2  <<<dim3(2, 32, 4),  256, G2_SMEM>>>();
    k_bt     <<<dim3(64, 4),     256>>>(bt_w, bt_b, bn2_g, bn2_b, bn2_m, bn2_v,
                                        prelu2, (float*)d_out);
}

// round 9
// speedup vs baseline: 1.2380x; 1.2380x over previous
#include <cuda_runtime.h>
#include <cuda_fp16.h>
#include <cstdint>

#define BATCH 4
#define NPIX  4096
#define CATT  128
#define EPS   1e-5f

// ---------------- device scratch ------------------------------------------
__device__ float g_tmp[BATCH * 16 * 128 * 128];
__device__ float g_f  [BATCH * 48 * NPIX];
__device__ __half g_q [(size_t)BATCH * NPIX * CATT];    // [b][i][c]
__device__ __half g_k [(size_t)BATCH * NPIX * CATT];    // [b][j][c]
__device__ __half g_v [(size_t)BATCH * CATT * NPIX];    // [b][c][j]
__device__ float g_ov [BATCH * CATT * NPIX];            // V*p, then += self_v

// ---------------- helpers --------------------------------------------------
__device__ __forceinline__ uint32_t smem_u32(const void* smem_ptr) {
    uint32_t addr;
    asm("{ .reg .u64 tmp; cvta.to.shared.u64 tmp, %1; cvt.u32.u64 %0, tmp; }"
        : "=r"(addr) : "l"(smem_ptr));
    return addr;
}
__device__ __forceinline__ void ldmx4(uint32_t* r, uint32_t addr) {
    asm volatile("ldmatrix.sync.aligned.m8n8.x4.shared.b16 {%0,%1,%2,%3}, [%4];"
        : "=r"(r[0]), "=r"(r[1]), "=r"(r[2]), "=r"(r[3]) : "r"(addr));
}
__device__ __forceinline__ void mma16816(float* c, const uint32_t* a,
                                         const uint32_t* b) {
    asm volatile(
        "mma.sync.aligned.m16n8k16.row.col.f32.f16.f16.f32 "
        "{%0,%1,%2,%3}, {%4,%5,%6,%7}, {%8,%9}, {%0,%1,%2,%3};"
        : "+f"(c[0]), "+f"(c[1]), "+f"(c[2]), "+f"(c[3])
        : "r"(a[0]), "r"(a[1]), "r"(a[2]), "r"(a[3]), "r"(b[0]), "r"(b[1]));
}
__device__ __forceinline__ void cp16(uint32_t dst, const void* src) {
    asm volatile("cp.async.ca.shared.global [%0], [%1], 16;"
                 :: "r"(dst), "l"(src) : "memory");
}
#define CP_COMMIT() asm volatile("cp.async.commit_group;" ::: "memory")
#define CP_WAIT1()  asm volatile("cp.async.wait_group 1;" ::: "memory")
#define CP_WAIT0()  asm volatile("cp.async.wait_group 0;" ::: "memory")

#define STF 136                     // half row stride (272B, ldmatrix-safe)
#define TILE_B (128 * STF * 2)      // 34816 B per 128x128 fp16 tile
#define FU_SMEM (5 * TILE_B)        // Q + 2xK + 2xV = 174080 B

__device__ __forceinline__ uint32_t pk2h(float a, float b) {
    __half2 h = __floats2half2_rn(a, b);
    return *(uint32_t*)&h;
}

// ---------------------------------------------------------------------------
// Kernel 1: conv3x3 + BN + PReLU
// ---------------------------------------------------------------------------
__global__ __launch_bounds__(256) void k_conv3(
    const float* __restrict__ em, const float* __restrict__ en_w,
    const float* __restrict__ en_b, const float* __restrict__ bn1_g,
    const float* __restrict__ bn1_b, const float* __restrict__ bn1_m,
    const float* __restrict__ bn1_v, const float* __restrict__ prelu1)
{
    __shared__ float ws[16 * 64 * 9];
    __shared__ float tile[4][18 * 18];
    const int tid = threadIdx.y * 16 + threadIdx.x;
    for (int idx = tid; idx < 16 * 64 * 9; idx += 256) ws[idx] = en_w[idx];

    const int b  = blockIdx.z;
    const int gx = blockIdx.x * 16 + threadIdx.x;
    const int gy = blockIdx.y * 16 + threadIdx.y;

    float acc[16];
#pragma unroll
    for (int o = 0; o < 16; o++) acc[o] = 0.f;
    const float* emb = em + (size_t)b * 64 * 128 * 128;

    for (int ci0 = 0; ci0 < 64; ci0 += 4) {
        __syncthreads();
        for (int idx = tid; idx < 4 * 324; idx += 256) {
            int c = idx / 324, rem = idx - c * 324;
            int r = rem / 18, cc = rem - r * 18;
            int yy = (int)blockIdx.y * 16 + r - 1;
            int xx = (int)blockIdx.x * 16 + cc - 1;
            float v = 0.f;
            if (yy >= 0 && yy < 128 && xx >= 0 && xx < 128)
                v = emb[(size_t)(ci0 + c) * 16384 + yy * 128 + xx];
            tile[c][rem] = v;
        }
        __syncthreads();
#pragma unroll
        for (int c = 0; c < 4; c++) {
            float t[9];
#pragma unroll
            for (int kh = 0; kh < 3; kh++)
#pragma unroll
                for (int kw = 0; kw < 3; kw++)
                    t[kh * 3 + kw] = tile[c][(threadIdx.y + kh) * 18 + threadIdx.x + kw];
            const float* w = ws + (ci0 + c) * 9;
#pragma unroll
            for (int o = 0; o < 16; o++)
#pragma unroll
                for (int k = 0; k < 9; k++)
                    acc[o] = fmaf(w[o * 576 + k], t[k], acc[o]);
        }
    }

    const float a = prelu1[0];
#pragma unroll
    for (int o = 0; o < 16; o++) {
        float y  = acc[o] + en_b[o];
        float sc = bn1_g[o] * rsqrtf(bn1_v[o] + EPS);
        y = (y - bn1_m[o]) * sc + bn1_b[o];
        y = (y >= 0.f) ? y : a * y;
        g_tmp[(((size_t)b * 16 + o) * 128 + gy) * 128 + gx] = y;
    }
}

// ---------------------------------------------------------------------------
// Kernel 2: build f
// ---------------------------------------------------------------------------
__global__ __launch_bounds__(256) void k_build_f(
    const float* __restrict__ dm, const float* __restrict__ de_w,
    const float* __restrict__ de_b, const float* __restrict__ dw_w,
    const float* __restrict__ dw_b)
{
    const int b  = blockIdx.z;
    const int ch = blockIdx.y;
    const int i  = blockIdx.x * 256 + threadIdx.x;
    float out;
    if (ch < 16) {
        const int ph = i >> 6, pw = i & 63;
        float m = -1e30f;
        const float* tb = g_tmp + ((size_t)b * 16 + ch) * 16384;
#pragma unroll
        for (int dy = 0; dy < 3; dy++) {
            int y = 2 * ph - 1 + dy;
            if (y < 0 || y > 127) continue;
#pragma unroll
            for (int dx = 0; dx < 3; dx++) {
                int x = 2 * pw - 1 + dx;
                if (x < 0 || x > 127) continue;
                m = fmaxf(m, tb[y * 128 + x]);
            }
        }
        out = m * dw_w[ch] + dw_b[ch];
    } else {
        const int co = ch - 16;
        float accv = de_b[co];
        const float* dmb = dm + (size_t)b * 128 * NPIX + i;
        const float* w   = de_w + co * 128;
#pragma unroll 8
        for (int c = 0; c < 128; c++)
            accv = fmaf(__ldg(w + c), __ldg(dmb + (size_t)c * NPIX), accv);
        out = accv;
    }
    g_f[((size_t)b * 48 + ch) * NPIX + i] = out;
}

// ---------------------------------------------------------------------------
// Kernel 3: QKV -> fp16 planes (+ g_ov = V*p)
// ---------------------------------------------------------------------------
__global__ __launch_bounds__(256) void k_qkv_t(
    const float* __restrict__ q_w, const float* __restrict__ q_b,
    const float* __restrict__ k_w, const float* __restrict__ k_b,
    const float* __restrict__ v_w, const float* __restrict__ v_b,
    const float* __restrict__ p)
{
    __shared__ float ws[128 * 48];
    __shared__ float bsm[128];
    const int b    = blockIdx.z;
    const int proj = blockIdx.y;
    const int tid  = threadIdx.x;
    const int i    = blockIdx.x * 256 + tid;

    const float* w  = (proj == 0) ? q_w : (proj == 1) ? k_w : v_w;
    const float* bb = (proj == 0) ? q_b : (proj == 1) ? k_b : v_b;
    for (int idx = tid; idx < 128 * 48; idx += 256) ws[idx] = w[idx];
    if (tid < 128) bsm[tid] = bb[tid];
    __syncthreads();

    float fv[48];
#pragma unroll
    for (int k = 0; k < 48; k++)
        fv[k] = g_f[((size_t)b * 48 + k) * NPIX + i];

    if (proj < 2) {
        __half* dst = ((proj == 0) ? g_q : g_k) + ((size_t)b * NPIX + i) * CATT;
        for (int c8 = 0; c8 < 16; c8++) {
            uint4 pkt;
            __half* hb = (__half*)&pkt;
#pragma unroll
            for (int cc = 0; cc < 8; cc++) {
                int c = c8 * 8 + cc;
                float accv = bsm[c];
                const float* wr = ws + c * 48;
#pragma unroll
                for (int k = 0; k < 48; k++)
                    accv = fmaf(wr[k], fv[k], accv);
                hb[cc] = __float2half_rn(accv);
            }
            *(uint4*)(dst + c8 * 8) = pkt;
        }
    } else {
        const float pv = p[(size_t)b * NPIX + i];
        for (int c = 0; c < 128; c++) {
            float accv = bsm[c];
            const float* wr = ws + c * 48;
#pragma unroll
            for (int k = 0; k < 48; k++)
                accv = fmaf(wr[k], fv[k], accv);
            size_t off = ((size_t)b * CATT + c) * NPIX + i;
            g_v[off]  = __float2half_rn(accv);
            g_ov[off] = accv * pv;
        }
    }
}

// ---------------------------------------------------------------------------
// Kernel 4: FUSED attention: g_ov[c][i] += sum_j sigmoid(Q_i·K_j) V[c][j]
// grid (32 it, 4 b), 256 thr (8 warps x m16), 174KB dyn smem, 1 CTA/SM.
// Distance-1 double buffering (stage jc+1 into the OTHER buffer, then WAIT1).
// ---------------------------------------------------------------------------
__global__ __launch_bounds__(256) void k_fused()
{
    extern __shared__ char smem[];
    const uint32_t su = smem_u32(smem);

    const int tid  = threadIdx.x;
    const int lane = tid & 31;
    const int warp = tid >> 5;
    const int wm   = warp * 16;
    const int b    = blockIdx.y;
    const int i0   = blockIdx.x * 128;

    const __half* Qg = g_q + ((size_t)b * NPIX + i0) * CATT;
    const __half* Kg = g_k + (size_t)b * NPIX * CATT;
    const __half* Vg = g_v + (size_t)b * CATT * NPIX;

    // stage Q together with KV chunk 0 (one group)
#pragma unroll
    for (int t = 0; t < 8; t++) {
        int idx = tid + t * 256;
        int r = idx >> 4, s = (idx & 15) * 8;
        cp16(su + (uint32_t)(r * STF + s) * 2, Qg + (size_t)r * CATT + s);
    }
    auto stageKV = [&](int buf, int j0) {
        uint32_t kb = su + (uint32_t)(1 + buf) * TILE_B;
        uint32_t vb = su + (uint32_t)(3 + buf) * TILE_B;
#pragma unroll
        for (int t = 0; t < 8; t++) {
            int idx = tid + t * 256;
            int r = idx >> 4, s = (idx & 15) * 8;
            cp16(kb + (uint32_t)(r * STF + s) * 2,
                 Kg + ((size_t)(j0 + r)) * CATT + s);
            cp16(vb + (uint32_t)(r * STF + s) * 2,
                 Vg + (size_t)r * NPIX + j0 + s);
        }
        CP_COMMIT();
    };
    stageKV(0, 0);      // group 0 = Q + KV0

    float oacc[16][4];
#pragma unroll
    for (int t = 0; t < 16; t++)
#pragma unroll
        for (int q = 0; q < 4; q++) oacc[t][q] = 0.f;

    const uint32_t a_row = (uint32_t)(wm + (lane & 15)) * STF +
                           ((uint32_t)(lane >> 4) << 3);
    const uint32_t b_row = (uint32_t)((lane & 7) + ((lane >> 4) << 3)) * STF +
                           (((uint32_t)(lane >> 3) & 1) << 3);

    for (int jc = 0; jc < 32; jc++) {
        if (jc < 31) { stageKV((jc + 1) & 1, (jc + 1) * 128); CP_WAIT1(); }
        else         { CP_WAIT0(); }
        __syncthreads();
        const uint32_t kb = su + (uint32_t)(1 + (jc & 1)) * TILE_B;
        const uint32_t vb = su + (uint32_t)(3 + (jc & 1)) * TILE_B;

        // ---- phase 1: S = Q · K^T (m16 x n128, k=128) ----
        float sacc[16][4];
#pragma unroll
        for (int t = 0; t < 16; t++)
#pragma unroll
            for (int q = 0; q < 4; q++) sacc[t][q] = 0.f;

#pragma unroll
        for (int kt = 0; kt < 8; kt++) {
            uint32_t aq[4];
            ldmx4(aq, su + (a_row + kt * 16) * 2);
#pragma unroll
            for (int nt = 0; nt < 8; nt++) {
                uint32_t bk[4];
                ldmx4(bk, kb + (b_row + (uint32_t)nt * 16 * STF + kt * 16) * 2);
                mma16816(sacc[2 * nt],     aq, bk);
                mma16816(sacc[2 * nt + 1], aq, bk + 2);
            }
        }

        // ---- sigmoid in registers ----
#pragma unroll
        for (int t = 0; t < 16; t++)
#pragma unroll
            for (int q = 0; q < 4; q++)
                sacc[t][q] = __fdividef(1.f, 1.f + __expf(-sacc[t][q]));

        // ---- phase 2: O += S · V^T (A fragments from S registers) ----
#pragma unroll
        for (int ktj = 0; ktj < 8; ktj++) {
            uint32_t as[4];
            as[0] = pk2h(sacc[2 * ktj][0],     sacc[2 * ktj][1]);
            as[1] = pk2h(sacc[2 * ktj][2],     sacc[2 * ktj][3]);
            as[2] = pk2h(sacc[2 * ktj + 1][0], sacc[2 * ktj + 1][1]);
            as[3] = pk2h(sacc[2 * ktj + 1][2], sacc[2 * ktj + 1][3]);
#pragma unroll
            for (int nc = 0; nc < 8; nc++) {
                uint32_t bv[4];
                ldmx4(bv, vb + (b_row + (uint32_t)nc * 16 * STF + ktj * 16) * 2);
                mma16816(oacc[2 * nc],     as, bv);
                mma16816(oacc[2 * nc + 1], as, bv + 2);
            }
        }
        __syncthreads();
    }

    // ---- epilogue: transpose O via smem, coalesced += into g_ov ----
    float* sst = (float*)(smem + TILE_B);   // 128 x 132 f32 (reuses K/V space)
#pragma unroll
    for (int nc = 0; nc < 16; nc++) {
        int c = nc * 8 + 2 * (lane & 3);
        int r = wm + (lane >> 2);
        sst[c * 132 + r]           = oacc[nc][0];
        sst[(c + 1) * 132 + r]     = oacc[nc][1];
        sst[c * 132 + r + 8]       = oacc[nc][2];
        sst[(c + 1) * 132 + r + 8] = oacc[nc][3];
    }
    __syncthreads();
    float* og = g_ov + ((size_t)b * CATT) * NPIX + i0;
    for (int idx = tid; idx < 128 * 128; idx += 256) {
        int c = idx >> 7, ii = idx & 127;
        og[(size_t)c * NPIX + ii] += sst[c * 132 + ii];
    }
}

// ---------------------------------------------------------------------------
// Kernel 5: bottleneck 1x1 + BN + PReLU -> out
// ---------------------------------------------------------------------------
__global__ __launch_bounds__(256) void k_bt(
    const float* __restrict__ bt_w, const float* __restrict__ bt_b,
    const float* __restrict__ bn2_g, const float* __restrict__ bn2_b,
    const float* __restrict__ bn2_m, const float* __restrict__ bn2_v,
    const float* __restrict__ prelu2, float* __restrict__ out)
{
    __shared__ float ovs[128][64];
    const int b  = blockIdx.y;
    const int i0 = blockIdx.x * 64;
    const int tid = threadIdx.x;

    for (int idx = tid; idx < 128 * 64; idx += 256) {
        int c = idx >> 6, ii = idx & 63;
        ovs[c][ii] = g_ov[((size_t)b * CATT + c) * NPIX + i0 + ii];
    }
    __syncthreads();

    const int il = tid & 63, og = tid >> 6;
    float accs[16];
#pragma unroll
    for (int n = 0; n < 16; n++) accs[n] = 0.f;

    for (int c = 0; c < 128; c++) {
        float v = ovs[c][il];
#pragma unroll
        for (int n = 0; n < 16; n++)
            accs[n] = fmaf(__ldg(bt_w + (og * 16 + n) * 128 + c), v, accs[n]);
    }

    const float a = prelu2[0];
#pragma unroll
    for (int n = 0; n < 16; n++) {
        int o = og * 16 + n;
        float y  = accs[n] + bt_b[o];
        float sc = bn2_g[o] * rsqrtf(bn2_v[o] + EPS);
        y = (y - bn2_m[o]) * sc + bn2_b[o];
        y = (y >= 0.f) ? y : a * y;
        out[((size_t)b * 64 + o) * NPIX + i0 + il] = y;
    }
}

// ---------------------------------------------------------------------------
extern "C" void kernel_launch(void* const* d_in, const int* in_sizes, int n_in,
                              void* d_out, int out_size)
{
    const float* em     = (const float*)d_in[0];
    const float* dm     = (const float*)d_in[1];
    const float* p      = (const float*)d_in[2];
    const float* en_w   = (const float*)d_in[3];
    const float* en_b   = (const float*)d_in[4];
    const float* bn1_g  = (const float*)d_in[5];
    const float* bn1_b  = (const float*)d_in[6];
    const float* bn1_m  = (const float*)d_in[7];
    const float* bn1_v  = (const float*)d_in[8];
    const float* prelu1 = (const float*)d_in[9];
    const float* dw_w   = (const float*)d_in[10];
    const float* dw_b   = (const float*)d_in[11];
    const float* de_w   = (const float*)d_in[12];
    const float* de_b   = (const float*)d_in[13];
    const float* q_w    = (const float*)d_in[14];
    const float* q_b    = (const float*)d_in[15];
    const float* k_w    = (const float*)d_in[16];
    const float* k_b    = (const float*)d_in[17];
    const float* v_w    = (const float*)d_in[18];
    const float* v_b    = (const float*)d_in[19];
    const float* bt_w   = (const float*)d_in[20];
    const float* bt_b   = (const float*)d_in[21];
    const float* bn2_g  = (const float*)d_in[22];
    const float* bn2_b  = (const float*)d_in[23];
    const float* bn2_m  = (const float*)d_in[24];
    const float* bn2_v  = (const float*)d_in[25];
    const float* prelu2 = (const float*)d_in[26];

    cudaFuncSetAttribute(k_fused, cudaFuncAttributeMaxDynamicSharedMemorySize,
                         FU_SMEM);

    k_conv3  <<<dim3(8, 8, 4),   dim3(16, 16)>>>(em, en_w, en_b, bn1_g, bn1_b,
                                                 bn1_m, bn1_v, prelu1);
    k_build_f<<<dim3(16, 48, 4), 256>>>(dm, de_w, de_b, dw_w, dw_b);
    k_qkv_t  <<<dim3(16, 3, 4),  256>>>(q_w, q_b, k_w, k_b, v_w, v_b, p);
    k_fused  <<<dim3(32, 4),     256, FU_SMEM>>>();
    k_bt     <<<dim3(64, 4),     256>>>(bt_w, bt_b, bn2_g, bn2_b, bn2_m, bn2_v,
                                        prelu2, (float*)d_out);
}